// round 4
// baseline (speedup 1.0000x reference)
#include <cuda_runtime.h>

// Problem constants
#define BB 8
#define CC 64
#define HH 256
#define WW 256
#define TW 16
#define TILES_PER_B (WW / TW)        // 16
#define NCTA (BB * TILES_PER_B)      // 128 persistent CTAs (<= 148 SMs -> all wave-1 resident)
#define NTHREADS 256
#define NWARPS 8
#define CIN_PER_WARP (CC / NWARPS)   // 8

#define YB_STRIDE 20                 // prev-row smem row stride (floats), 80B (16B aligned)
#define PB_STRIDE 21                 // partial buffer stride (floats), odd-ish to dodge bank conflicts
#define SMEM_FLOATS (2 * CC * YB_STRIDE + NWARPS * CC * PB_STRIDE)  // 2560 + 10752 = 13312
#define SMEM_BYTES (SMEM_FLOATS * 4) // 53248

// Per-CTA progress flags: flags[cta] = number of rows published to gmem.
__device__ int g_flags[NCTA];

__device__ __forceinline__ int ld_acquire_i32(const int* p) {
    int v;
    asm volatile("ld.acquire.gpu.b32 %0, [%1];" : "=r"(v) : "l"(p) : "memory");
    return v;
}
__device__ __forceinline__ void st_release_i32(int* p, int v) {
    asm volatile("st.release.gpu.b32 [%0], %1;" :: "l"(p), "r"(v) : "memory");
}
__device__ __forceinline__ float ld_acquire_f32(const float* p) {
    float v;
    asm volatile("ld.acquire.gpu.f32 %0, [%1];" : "=f"(v) : "l"(p) : "memory");
    return v;
}

__global__ void zero_flags_kernel() {
    int i = threadIdx.x;
    if (i < NCTA) g_flags[i] = 0;
}

__global__ void __launch_bounds__(NTHREADS, 1)
spatial_conv_kernel(const float* __restrict__ X,
                    const float* __restrict__ Wc,
                    const float* __restrict__ bc,
                    float* __restrict__ Y)
{
    extern __shared__ float smem[];
    float* ybuf = smem;                         // [2][CC][YB_STRIDE]; col 0 = left halo (kept 0), 1..16 interior, 17 right halo (kept 0)
    float* pbuf = smem + 2 * CC * YB_STRIDE;    // [NWARPS][CC][PB_STRIDE]

    const int cta  = blockIdx.x;
    const int b    = cta / TILES_PER_B;
    const int t    = cta % TILES_PER_B;
    const int w0   = t * TW;
    const int tid  = threadIdx.x;
    const int warp = tid >> 5;
    const int lane = tid & 31;
    const int cinBase = warp * CIN_PER_WARP;

    // ---- Weights fully register-resident: lane owns couts {2*lane, 2*lane+1}, warp owns 8 cins ----
    float wr[2][CIN_PER_WARP][3];
    #pragma unroll
    for (int c2 = 0; c2 < 2; c2++)
        #pragma unroll
        for (int j = 0; j < CIN_PER_WARP; j++)
            #pragma unroll
            for (int k = 0; k < 3; k++)
                wr[c2][j][k] = Wc[((2 * lane + c2) * CC + (cinBase + j)) * 3 + k];

    // Zero ybuf (both buffers, including halo columns which stay zero forever)
    for (int i = tid; i < 2 * CC * YB_STRIDE; i += NTHREADS) ybuf[i] = 0.0f;
    __syncthreads();

    // ---- Reduce-phase mapping: thread handles cout=cr, w-quad q (4 contiguous w) ----
    const int cr = tid >> 2;   // 0..63
    const int q  = tid & 3;    // 0..3
    const float bias = bc[cr];
    const long rowBase = ((long)b * CC + cr) * HH;   // X/Y index: (rowBase + h)*WW + w0 + 4q

    // ---- Row 0: Y[0] = X[0] ----
    {
        const float4 x4 = *(const float4*)&X[(rowBase + 0) * WW + w0 + 4 * q];
        *(float4*)&Y[(rowBase + 0) * WW + w0 + 4 * q] = x4;
        float* yb = &ybuf[(0 * CC + cr) * YB_STRIDE + 1 + 4 * q];
        yb[0] = x4.x; yb[1] = x4.y; yb[2] = x4.z; yb[3] = x4.w;
    }
    __syncthreads();
    if (tid == 0) st_release_i32(&g_flags[cta], 1);

    const int leftF  = (t > 0) ? cta - 1 : -1;
    const int rightF = (t < TILES_PER_B - 1) ? cta + 1 : -1;

    for (int h = 1; h < HH; h++) {
        const int pb = (h - 1) & 1;
        const int cb = h & 1;

        // Prefetch X row tile early (DRAM latency hides under mainloop)
        const float4 x4 = *(const float4*)&X[(rowBase + h) * WW + w0 + 4 * q];

        // ---- Mainloop: partial conv over this warp's 8 cins, halo taps see zeros ----
        float acc0[TW], acc1[TW];
        #pragma unroll
        for (int w = 0; w < TW; w++) { acc0[w] = 0.0f; acc1[w] = 0.0f; }

        const float* ybase = &ybuf[pb * CC * YB_STRIDE];
        #pragma unroll
        for (int j = 0; j < CIN_PER_WARP; j++) {
            const float* yr = ybase + (cinBase + j) * YB_STRIDE;
            float yv[18];
            {
                const float4 a  = *(const float4*)(yr + 0);
                const float4 b4 = *(const float4*)(yr + 4);
                const float4 c4 = *(const float4*)(yr + 8);
                const float4 d4 = *(const float4*)(yr + 12);
                const float2 e2 = *(const float2*)(yr + 16);
                yv[0]=a.x;  yv[1]=a.y;  yv[2]=a.z;  yv[3]=a.w;
                yv[4]=b4.x; yv[5]=b4.y; yv[6]=b4.z; yv[7]=b4.w;
                yv[8]=c4.x; yv[9]=c4.y; yv[10]=c4.z; yv[11]=c4.w;
                yv[12]=d4.x; yv[13]=d4.y; yv[14]=d4.z; yv[15]=d4.w;
                yv[16]=e2.x; yv[17]=e2.y;
            }
            #pragma unroll
            for (int w = 0; w < TW; w++) {
                acc0[w] = fmaf(wr[0][j][0], yv[w],     acc0[w]);
                acc0[w] = fmaf(wr[0][j][1], yv[w + 1], acc0[w]);
                acc0[w] = fmaf(wr[0][j][2], yv[w + 2], acc0[w]);
                acc1[w] = fmaf(wr[1][j][0], yv[w],     acc1[w]);
                acc1[w] = fmaf(wr[1][j][1], yv[w + 1], acc1[w]);
                acc1[w] = fmaf(wr[1][j][2], yv[w + 2], acc1[w]);
            }
        }

        // ---- Wait for neighbors to have published row h-1 (usually already true) ----
        if (leftF >= 0)  { while (ld_acquire_i32(&g_flags[leftF])  < h) __nanosleep(64); }
        if (rightF >= 0) { while (ld_acquire_i32(&g_flags[rightF]) < h) __nanosleep(64); }

        // ---- Halo corrections from gmem Y (row h-1, L2-hit, broadcast across lanes) ----
        if (leftF >= 0) {
            #pragma unroll
            for (int j = 0; j < CIN_PER_WARP; j++) {
                const float yl = ld_acquire_f32(
                    &Y[(((long)b * CC + cinBase + j) * HH + (h - 1)) * WW + (w0 - 1)]);
                acc0[0] = fmaf(wr[0][j][0], yl, acc0[0]);
                acc1[0] = fmaf(wr[1][j][0], yl, acc1[0]);
            }
        }
        if (rightF >= 0) {
            #pragma unroll
            for (int j = 0; j < CIN_PER_WARP; j++) {
                const float yrh = ld_acquire_f32(
                    &Y[(((long)b * CC + cinBase + j) * HH + (h - 1)) * WW + (w0 + TW)]);
                acc0[TW - 1] = fmaf(wr[0][j][2], yrh, acc0[TW - 1]);
                acc1[TW - 1] = fmaf(wr[1][j][2], yrh, acc1[TW - 1]);
            }
        }

        // ---- Store partials ----
        {
            float* p0 = &pbuf[(warp * CC + 2 * lane) * PB_STRIDE];
            #pragma unroll
            for (int w = 0; w < TW; w++) {
                p0[w]             = acc0[w];
                p0[PB_STRIDE + w] = acc1[w];
            }
        }
        __syncthreads();

        // ---- Reduce 8 warps, +bias, tanh, +X; write smem (next prev-row) and gmem Y ----
        {
            float res[4];
            const float xr[4] = {x4.x, x4.y, x4.z, x4.w};
            #pragma unroll
            for (int i = 0; i < 4; i++) {
                const int w = 4 * q + i;
                float s = bias;
                #pragma unroll
                for (int p = 0; p < NWARPS; p++)
                    s += pbuf[(p * CC + cr) * PB_STRIDE + w];
                res[i] = xr[i] + tanhf(s);
                ybuf[(cb * CC + cr) * YB_STRIDE + 1 + w] = res[i];
            }
            float4 o4; o4.x = res[0]; o4.y = res[1]; o4.z = res[2]; o4.w = res[3];
            *(float4*)&Y[(rowBase + h) * WW + w0 + 4 * q] = o4;
        }
        __syncthreads();  // gmem stores + ybuf complete; pbuf safe to reuse next row

        if (tid == 0) st_release_i32(&g_flags[cta], h + 1);
    }
}

extern "C" void kernel_launch(void* const* d_in, const int* in_sizes, int n_in,
                              void* d_out, int out_size)
{
    const float* X  = (const float*)d_in[0];
    const float* Wc = (const float*)d_in[1];
    const float* bc = (const float*)d_in[2];
    float* Y = (float*)d_out;

    cudaFuncSetAttribute(spatial_conv_kernel,
                         cudaFuncAttributeMaxDynamicSharedMemorySize, SMEM_BYTES);

    zero_flags_kernel<<<1, 128>>>();
    spatial_conv_kernel<<<NCTA, NTHREADS, SMEM_BYTES>>>(X, Wc, bc, Y);
}

// round 8
// speedup vs baseline: 1.6229x; 1.6229x over previous
#include <cuda_runtime.h>

#define BB 8
#define CC 64
#define HH 256
#define WW 256
#define TW 16
#define TILES_PER_B 16              // 256 / 16
#define NCTA 128                    // 8 batches x 16 tiles, all wave-1 resident (128 < 148 SMs)
#define NTHREADS 256

#define EW 18                       // extended width: w = -1 .. 16
#define YB (EW * CC)                // floats per row buffer (1152)

// Per-CTA progress: flags[cta] = number of rows fully published to gmem (R4-proven protocol)
__device__ int g_flags[NCTA];

__device__ __forceinline__ int ld_acquire_i32(const int* p) {
    int v;
    asm volatile("ld.acquire.gpu.b32 %0, [%1];" : "=r"(v) : "l"(p) : "memory");
    return v;
}
__device__ __forceinline__ void st_release_i32(int* p, int v) {
    asm volatile("st.release.gpu.b32 [%0], %1;" :: "l"(p), "r"(v) : "memory");
}
__device__ __forceinline__ unsigned long long pack2(float lo, float hi) {
    unsigned long long r;
    asm("mov.b64 %0, {%1, %2};" : "=l"(r) : "f"(lo), "f"(hi));
    return r;
}
__device__ __forceinline__ void unpack2(unsigned long long v, float& lo, float& hi) {
    asm("mov.b64 {%0, %1}, %2;" : "=f"(lo), "=f"(hi) : "l"(v));
}
// Packed dual FMA: d.lo += a.lo*b.lo ; d.hi += a.hi*b.hi  (FFMA2, sm_100+)
__device__ __forceinline__ void ffma2(unsigned long long& d, unsigned long long a, unsigned long long b) {
    asm("fma.rn.f32x2 %0, %1, %2, %0;" : "+l"(d) : "l"(a), "l"(b));
}
// tanh via exp path; rel error ~1e-6/step, ~1e-5 accumulated over 255 rows — far under 1e-3
__device__ __forceinline__ float fast_tanh(float x) {
    float cx = fminf(fmaxf(x, -15.0f), 15.0f);
    float e = __expf(2.0f * cx);
    return __fdividef(e - 1.0f, e + 1.0f);
}
// R4-proven poll: acquire-load with nanosleep backoff
__device__ __forceinline__ void wait_flag(const int* p, int target) {
    while (ld_acquire_i32(p) < target) __nanosleep(64);
}

__global__ void zero_flags_kernel() {
    if (threadIdx.x < NCTA) g_flags[threadIdx.x] = 0;
}

__global__ void __launch_bounds__(NTHREADS, 1)
spatial_conv_kernel(const float* __restrict__ X,
                    const float* __restrict__ Wc,
                    const float* __restrict__ bc,
                    float* __restrict__ Y)
{
    // Prev/cur row, layout [buf][e][cin] — cin contiguous so an LDS.64 yields a cin-pair.
    // e=0 is the w=-1 halo, e=17 the w=16 halo; both stay zero (SAME padding; real
    // neighbor contributions are patched from gmem after the flag wait).
    __shared__ __align__(16) float ybuf[2 * YB];

    const int cta = blockIdx.x;
    const int b   = cta / TILES_PER_B;
    const int t   = cta % TILES_PER_B;
    const int w0  = t * TW;
    const int tid = threadIdx.x;
    const int cr  = tid >> 2;       // output channel 0..63
    const int q   = tid & 3;        // cin-quarter / w-quad owner

    // Weight pairs (packed once, outside the 255-row loop):
    // pair i covers cins (8i+2q, 8i+2q+1); wp[i][k] = (W[cr][c0][k], W[cr][c0+1][k])
    unsigned long long wp[8][3];
    #pragma unroll
    for (int i = 0; i < 8; i++) {
        const int c0 = 8 * i + 2 * q;
        #pragma unroll
        for (int k = 0; k < 3; k++)
            wp[i][k] = pack2(Wc[(cr * CC + c0) * 3 + k], Wc[(cr * CC + c0 + 1) * 3 + k]);
    }
    const float bias = bc[cr];

    for (int idx = tid; idx < 2 * YB; idx += NTHREADS) ybuf[idx] = 0.0f;

    // This thread's gmem base (channel = cr, columns w0+4q .. +3)
    const long rowBase = ((long)(b * CC + cr) * HH) * WW + w0 + 4 * q;
    // Halo source bases (channel plane c0 applied inside the patch loops; stride HH*WW)
    const float* const haloL = &Y[((long)(b * CC) * HH) * WW + (w0 - 1)];
    const float* const haloR = &Y[((long)(b * CC) * HH) * WW + (w0 + TW)];
    __syncthreads();

    // ---- Row 0: Y[0] = X[0] ----
    {
        const float4 x4 = *(const float4*)&X[rowBase];
        *(float4*)&Y[rowBase] = x4;
        float* yb = &ybuf[0];                      // buf 0
        yb[(4 * q + 1) * CC + cr] = x4.x;
        yb[(4 * q + 2) * CC + cr] = x4.y;
        yb[(4 * q + 3) * CC + cr] = x4.z;
        yb[(4 * q + 4) * CC + cr] = x4.w;
    }
    __syncthreads();
    if (tid == 0) st_release_i32(&g_flags[cta], 1);

    const int leftF  = (t > 0) ? cta - 1 : -1;
    const int rightF = (t < TILES_PER_B - 1) ? cta + 1 : -1;

    for (int h = 1; h < HH; h++) {
        const int pb = (h - 1) & 1;
        const int cb = h & 1;

        // Prefetch X tile for this row (needed only at finalize)
        const float4 x4 = *(const float4*)&X[rowBase + (long)h * WW];

        // ---- Packed mainloop: 16 cins (8 pairs) x 16 w x 3 taps, halos read zeros ----
        unsigned long long acc2[16];
        #pragma unroll
        for (int w = 0; w < 16; w++) acc2[w] = 0ULL;

        const float* ybase = &ybuf[pb * YB];
        #pragma unroll
        for (int i = 0; i < 8; i++) {
            const int c0 = 8 * i + 2 * q;
            unsigned long long yp[EW];
            #pragma unroll
            for (int e = 0; e < EW; e++)
                yp[e] = *(const unsigned long long*)(ybase + e * CC + c0);
            #pragma unroll
            for (int w = 0; w < 16; w++) {
                ffma2(acc2[w], yp[w],     wp[i][0]);
                ffma2(acc2[w], yp[w + 1], wp[i][1]);
                ffma2(acc2[w], yp[w + 2], wp[i][2]);
            }
        }

        // Combine even/odd cin planes
        float acc[16];
        #pragma unroll
        for (int w = 0; w < 16; w++) {
            float lo, hi;
            unpack2(acc2[w], lo, hi);
            acc[w] = lo + hi;
        }

        // ---- Wait for neighbors to publish row h-1 (usually already true) ----
        if (leftF  >= 0) wait_flag(&g_flags[leftF],  h);
        if (rightF >= 0) wait_flag(&g_flags[rightF], h);

        // ---- Halo corrections from gmem Y (row h-1, L2-hot, broadcast across cr lanes) ----
        const long hOff = (long)(h - 1) * WW;
        if (leftF >= 0) {
            #pragma unroll
            for (int i = 0; i < 8; i++) {
                const int c0 = 8 * i + 2 * q;
                float wa, wb; unpack2(wp[i][0], wa, wb);
                const float ya  = haloL[(long)c0 * (HH * WW) + hOff];
                const float yb2 = haloL[(long)(c0 + 1) * (HH * WW) + hOff];
                acc[0] = fmaf(wa, ya, acc[0]);
                acc[0] = fmaf(wb, yb2, acc[0]);
            }
        }
        if (rightF >= 0) {
            #pragma unroll
            for (int i = 0; i < 8; i++) {
                const int c0 = 8 * i + 2 * q;
                float wa, wb; unpack2(wp[i][2], wa, wb);
                const float ya  = haloR[(long)c0 * (HH * WW) + hOff];
                const float yb2 = haloR[(long)(c0 + 1) * (HH * WW) + hOff];
                acc[15] = fmaf(wa, ya, acc[15]);
                acc[15] = fmaf(wb, yb2, acc[15]);
            }
        }

        // ---- Reduce-scatter over the 4 q-lanes (12 shfl total) ----
        const bool hi2 = (q & 2) != 0;
        float r8[8];
        #pragma unroll
        for (int s = 0; s < 8; s++) {
            const float sv = hi2 ? acc[s] : acc[s + 8];
            const float rv = __shfl_xor_sync(0xFFFFFFFFu, sv, 2);
            const float kv = hi2 ? acc[s + 8] : acc[s];
            r8[s] = kv + rv;
        }
        const bool hi1 = (q & 1) != 0;
        float r4[4];
        #pragma unroll
        for (int s = 0; s < 4; s++) {
            const float sv = hi1 ? r8[s] : r8[s + 4];
            const float rv = __shfl_xor_sync(0xFFFFFFFFu, sv, 1);
            const float kv = hi1 ? r8[s + 4] : r8[s];
            r4[s] = kv + rv;
        }
        // lane q now owns final sums for w = 4q+s

        // ---- Finalize: +bias, tanh, +X; write smem (next prev-row) and gmem Y ----
        float res[4];
        const float xr[4] = {x4.x, x4.y, x4.z, x4.w};
        float* yb = &ybuf[cb * YB];
        #pragma unroll
        for (int s = 0; s < 4; s++) {
            res[s] = xr[s] + fast_tanh(r4[s] + bias);
            yb[(4 * q + s + 1) * CC + cr] = res[s];
        }
        const float4 o4 = {res[0], res[1], res[2], res[3]};
        *(float4*)&Y[rowBase + (long)h * WW] = o4;

        __syncthreads();   // ybuf[cb] + all Y stores complete before publish / next row
        if (tid == 0) st_release_i32(&g_flags[cta], h + 1);
    }
}

extern "C" void kernel_launch(void* const* d_in, const int* in_sizes, int n_in,
                              void* d_out, int out_size)
{
    const float* X  = (const float*)d_in[0];
    const float* Wc = (const float*)d_in[1];
    const float* bc = (const float*)d_in[2];
    float* Y = (float*)d_out;

    zero_flags_kernel<<<1, 128>>>();
    spatial_conv_kernel<<<NCTA, NTHREADS>>>(X, Wc, bc, Y);
}